// round 1
// baseline (speedup 1.0000x reference)
#include <cuda_runtime.h>

// ============================================================================
// HelixMemory decomposition:
//   out[b, 0:254]      = cm[r]    = memory[2r+2] @ F0 + memory[2r+3] @ F1   (batch-independent)
//   out[b, 254:510]    = cx[b,t]  = x[b,2t] @ F0 + x[b,2t+1] @ F1
//   out[b, 510:2046]   = memory[1022:2558]                                  (batch-independent)
//   out[b, 2046:2558]  = x[b]
// Both compress ops are a single GEMM A(M,2048) @ F(2048,1024):
//   A = inputs viewed (8192, 2048) contiguous; A = memory+2*D viewed (254, 2048).
// ============================================================================

namespace {
constexpr int D        = 1024;
constexpr int KDIM     = 2048;
constexpr int OUT_ROWS = 2558;
constexpr int CM_ROWS  = 254;
constexpr int BATCH    = 32;
constexpr int SEQ      = 512;

constexpr int BM = 128, BN = 128, BK = 8, TM = 8, TN = 8;
}

// batch-independent compressed-memory block scratch (254 x 1024 f32 = 1 MB)
__device__ float g_cm[CM_ROWS * D];

// ----------------------------------------------------------------------------
// SGEMM: C = A(M x 2048) * F(2048 x 1024)
// MODE 0: A = inputs (M = 8192), epilogue scatters into d_out with batch map
// MODE 1: A = memory + 2*D (M = 254), epilogue writes g_cm
// ----------------------------------------------------------------------------
template <int MODE>
__global__ __launch_bounds__(256) void gemm_kernel(
    const float* __restrict__ A, const float* __restrict__ F,
    float* __restrict__ out, int M)
{
    __shared__ float As[BK][BM];
    __shared__ float Bs[BK][BN];

    const int tid = threadIdx.x;
    const int bm  = blockIdx.y;
    const int bn  = blockIdx.x;

    const int tr = (tid / 16) * TM;   // row within blocktile
    const int tc = (tid % 16) * TN;   // col within blocktile

    // A tile load: 128x8, one float4 per thread
    const int aRow = tid / 2;
    const int aCol = (tid % 2) * 4;
    // F tile load: 8x128, one float4 per thread
    const int bRow = tid / 32;
    const int bCol = (tid % 32) * 4;

    // Note: for MODE 1 the last blocktile reads A rows up to 255; those rows
    // are physically inside the memory buffer (rows 2..513 of 2558), so loads
    // are safe — only stores are guarded.
    const float* Ap = A + (size_t)(bm * BM + aRow) * KDIM + aCol;
    const float* Fp = F + (size_t)bRow * D + bn * BN + bCol;

    float acc[TM][TN] = {};

    for (int kt = 0; kt < KDIM; kt += BK) {
        float4 av = *reinterpret_cast<const float4*>(Ap + kt);
        As[aCol + 0][aRow] = av.x;
        As[aCol + 1][aRow] = av.y;
        As[aCol + 2][aRow] = av.z;
        As[aCol + 3][aRow] = av.w;
        float4 fv = *reinterpret_cast<const float4*>(Fp + (size_t)kt * D);
        *reinterpret_cast<float4*>(&Bs[bRow][bCol]) = fv;
        __syncthreads();

        #pragma unroll
        for (int k = 0; k < BK; ++k) {
            float ra[TM], rb[TN];
            *reinterpret_cast<float4*>(&ra[0]) = *reinterpret_cast<const float4*>(&As[k][tr]);
            *reinterpret_cast<float4*>(&ra[4]) = *reinterpret_cast<const float4*>(&As[k][tr + 4]);
            *reinterpret_cast<float4*>(&rb[0]) = *reinterpret_cast<const float4*>(&Bs[k][tc]);
            *reinterpret_cast<float4*>(&rb[4]) = *reinterpret_cast<const float4*>(&Bs[k][tc + 4]);
            #pragma unroll
            for (int i = 0; i < TM; ++i)
                #pragma unroll
                for (int j = 0; j < TN; ++j)
                    acc[i][j] += ra[i] * rb[j];
        }
        __syncthreads();
    }

    #pragma unroll
    for (int i = 0; i < TM; ++i) {
        const int gr = bm * BM + tr + i;
        if (MODE == 1 && gr >= M) continue;
        float* dst;
        if (MODE == 0) {
            const int b = gr >> 8;        // batch
            const int t = gr & 255;       // compressed row within batch
            dst = out + ((size_t)b * OUT_ROWS + 254 + t) * D + bn * BN + tc;
        } else {
            dst = g_cm + (size_t)gr * D + bn * BN + tc;
        }
        reinterpret_cast<float4*>(dst)[0] =
            make_float4(acc[i][0], acc[i][1], acc[i][2], acc[i][3]);
        reinterpret_cast<float4*>(dst)[1] =
            make_float4(acc[i][4], acc[i][5], acc[i][6], acc[i][7]);
    }
}

// ----------------------------------------------------------------------------
// Copy/broadcast kernel: per batch,
//   rows 0:254       <- g_cm
//   rows 510:2046    <- memory[1022:2558]
//   rows 2046:2558   <- inputs[b]
// All in float4 units; everything is 16B-aligned (row length 1024 f32).
// ----------------------------------------------------------------------------
__global__ __launch_bounds__(256) void copy_kernel(
    const float* __restrict__ inputs, const float* __restrict__ memory,
    float* __restrict__ out)
{
    constexpr int F4     = D / 4;                       // 256 float4 per row
    constexpr int R_CM   = CM_ROWS * F4;                // 65024
    constexpr int R_MEM  = R_CM + 1536 * F4;            // + memory tail
    constexpr int PER_B  = (CM_ROWS + 1536 + SEQ) * F4; // 589312
    const int total = BATCH * PER_B;                    // ~18.9M, fits in int

    const float4* cm4  = reinterpret_cast<const float4*>(g_cm);
    const float4* mem4 = reinterpret_cast<const float4*>(memory);
    const float4* in4  = reinterpret_cast<const float4*>(inputs);
    float4*       out4 = reinterpret_cast<float4*>(out);

    for (int idx = blockIdx.x * blockDim.x + threadIdx.x; idx < total;
         idx += gridDim.x * blockDim.x) {
        const int b = idx / PER_B;
        const int r = idx - b * PER_B;
        float4 v;
        size_t dst;
        const size_t base = (size_t)b * OUT_ROWS * F4;
        if (r < R_CM) {
            v   = cm4[r];
            dst = base + r;
        } else if (r < R_MEM) {
            const int rr = r - R_CM;
            v   = mem4[1022 * F4 + rr];
            dst = base + 510 * F4 + rr;
        } else {
            const int rr = r - R_MEM;
            v   = in4[(size_t)b * SEQ * F4 + rr];
            dst = base + 2046 * F4 + rr;
        }
        out4[dst] = v;
    }
}

// ----------------------------------------------------------------------------
extern "C" void kernel_launch(void* const* d_in, const int* in_sizes, int n_in,
                              void* d_out, int out_size)
{
    const float* inputs  = (const float*)d_in[0];  // (32, 512, 1024)
    const float* memory  = (const float*)d_in[1];  // (2558, 1024)
    const float* filters = (const float*)d_in[2];  // (2, 1024, 1024) -> (2048, 1024)
    float* out = (float*)d_out;                    // (32, 2558, 1024)

    // 1) batch-independent compressed memory block (M = 254)
    gemm_kernel<1><<<dim3(D / BN, 2), 256>>>(memory + 2 * D, filters, out, CM_ROWS);
    // 2) compress(x) for all batches (M = 8192), written straight into out
    gemm_kernel<0><<<dim3(D / BN, (BATCH * 256) / BM), 256>>>(inputs, filters, out,
                                                              BATCH * 256);
    // 3) broadcast cm + memory tail + x passthrough
    copy_kernel<<<148 * 16, 256>>>(inputs, memory, out);
}

// round 4
// speedup vs baseline: 4.2611x; 4.2611x over previous
#include <cuda_runtime.h>
#include <cstdint>

// ============================================================================
// HelixMemory, portable-PTX tensor path (mma.sync tf32; no tcgen05 — harness
// compiles via compute_103 virtual arch which rejects sm_103a-only features):
//   out[b, 0:254]      = cm[r]   = memory[2r+2] @ F0 + memory[2r+3] @ F1
//   out[b, 254:510]    = cx[b,t] = x[b,2t] @ F0 + x[b,2t+1] @ F1
//   out[b, 510:2046]   = memory[1022:2558]
//   out[b, 2046:2558]  = x[b]
// Single GEMM, M = 8192 (inputs) + 256 (memory rows), N=1024, K=2048.
// B = filters viewed (2048, 1024) row-major == exactly the [k][n] layout the
// m16n8k8 row.col B-fragment wants. No transpose needed.
// ============================================================================

namespace {
constexpr int D_       = 1024;
constexpr int KDIM     = 2048;
constexpr int OUT_ROWS = 2558;
constexpr int CM_ROWS  = 254;
constexpr int BATCH    = 32;
constexpr int SEQ      = 512;

constexpr int BM = 128, BN = 128, BK = 32;
constexpr int STAGES = 3;
constexpr int KT = KDIM / BK;                    // 64

constexpr int A_PITCH = BK + 4;                  // 36 floats  (conflict-free)
constexpr int B_PITCH = BN + 8;                  // 136 floats (conflict-free)
constexpr int A_STAGE = BM * A_PITCH;            // 4608 floats
constexpr int B_STAGE = BK * B_PITCH;            // 4352 floats
constexpr int STAGE_FLOATS = A_STAGE + B_STAGE;  // 8960
constexpr int SMEM_BYTES = STAGES * STAGE_FLOATS * 4;  // 107520
}

__device__ __align__(128) float g_cm[CM_ROWS * D_];   // batch-independent block

// ---------------------------------------------------------------------------
__device__ __forceinline__ uint32_t smem_u32(const void* p) {
    uint32_t a;
    asm("{ .reg .u64 t; cvta.to.shared.u64 t, %1; cvt.u32.u64 %0, t; }" : "=r"(a) : "l"(p));
    return a;
}
__device__ __forceinline__ void cp16(uint32_t s, const float* g) {
    asm volatile("cp.async.cg.shared.global [%0], [%1], 16;" :: "r"(s), "l"(g));
}
__device__ __forceinline__ void mma_tf32(float* c, const float* a, const float* b) {
    asm volatile(
        "mma.sync.aligned.m16n8k8.row.col.f32.tf32.tf32.f32 "
        "{%0,%1,%2,%3}, {%4,%5,%6,%7}, {%8,%9}, {%0,%1,%2,%3};"
        : "+f"(c[0]), "+f"(c[1]), "+f"(c[2]), "+f"(c[3])
        : "r"(__float_as_uint(a[0])), "r"(__float_as_uint(a[1])),
          "r"(__float_as_uint(a[2])), "r"(__float_as_uint(a[3])),
          "r"(__float_as_uint(b[0])), "r"(__float_as_uint(b[1])));
}

// ---------------------------------------------------------------------------
// GEMM: grid (8 N-tiles, 66 M-tiles). bm<64 -> inputs (scatter into out),
// bm>=64 -> memory rows (write g_cm).
// ---------------------------------------------------------------------------
__global__ __launch_bounds__(256, 2) void helix_gemm(
    const float* __restrict__ A_in, const float* __restrict__ A_mem,
    const float* __restrict__ F, float* __restrict__ out)
{
    extern __shared__ float smem[];
    const uint32_t sbase = smem_u32(smem);

    const int tid  = threadIdx.x;
    const int wid  = tid >> 5;
    const int lane = tid & 31;
    const int g    = lane >> 2;       // group id (row within fragment)
    const int t    = lane & 3;        // thread-in-group
    const int wm   = wid & 3;         // 4 warps along M (32 rows each)
    const int wn   = wid >> 2;        // 2 warps along N (64 cols each)

    const int bn = blockIdx.x;
    const int bm = blockIdx.y;
    const int n0 = bn * BN;

    const float* Abase = (bm < 64) ? (A_in + (size_t)bm * BM * KDIM)
                                   : (A_mem + (size_t)(bm - 64) * BM * KDIM);

    // ---- async tile loader ------------------------------------------------
    auto issue = [&](int kt) {
        const int s = kt % STAGES;
        const uint32_t sA = sbase + (uint32_t)(s * STAGE_FLOATS) * 4;
        const uint32_t sB = sA + (uint32_t)A_STAGE * 4;
        const int k0 = kt * BK;
        #pragma unroll
        for (int i = 0; i < 4; ++i) {            // A: 128x32 = 1024 16B chunks
            const int q   = tid + 256 * i;
            const int row = q >> 3;
            const int c4  = q & 7;
            cp16(sA + (uint32_t)(row * A_PITCH + c4 * 4) * 4,
                 Abase + (size_t)row * KDIM + k0 + c4 * 4);
        }
        #pragma unroll
        for (int i = 0; i < 4; ++i) {            // B: 32x128 = 1024 16B chunks
            const int q   = tid + 256 * i;
            const int row = q >> 5;
            const int c4  = q & 31;
            cp16(sB + (uint32_t)(row * B_PITCH + c4 * 4) * 4,
                 F + (size_t)(k0 + row) * D_ + n0 + c4 * 4);
        }
        asm volatile("cp.async.commit_group;" ::: "memory");
    };

    float c[2][8][4] = {};

    // prefetch
    issue(0);
    issue(1);

    for (int kt = 0; kt < KT; ++kt) {
        asm volatile("cp.async.wait_group 1;" ::: "memory");
        __syncthreads();

        if (kt + STAGES - 1 < KT) issue(kt + STAGES - 1);

        const int s = kt % STAGES;
        const float* As = smem + s * STAGE_FLOATS;
        const float* Bs = As + A_STAGE;

        #pragma unroll
        for (int ks = 0; ks < 4; ++ks) {         // 4 x k8 steps = BK 32
            float a[2][4];
            #pragma unroll
            for (int mt = 0; mt < 2; ++mt) {
                const float* ap = As + (wm * 32 + mt * 16 + g) * A_PITCH + ks * 8 + t;
                a[mt][0] = ap[0];
                a[mt][1] = ap[8 * A_PITCH];
                a[mt][2] = ap[4];
                a[mt][3] = ap[8 * A_PITCH + 4];
            }
            float bf[8][2];
            #pragma unroll
            for (int nt = 0; nt < 8; ++nt) {
                const float* bp = Bs + (ks * 8 + t) * B_PITCH + wn * 64 + nt * 8 + g;
                bf[nt][0] = bp[0];
                bf[nt][1] = bp[4 * B_PITCH];
            }
            #pragma unroll
            for (int mt = 0; mt < 2; ++mt)
                #pragma unroll
                for (int nt = 0; nt < 8; ++nt)
                    mma_tf32(c[mt][nt], a[mt], bf[nt]);
        }
        __syncthreads();
    }

    // ---- epilogue: float2 stores ------------------------------------------
    #pragma unroll
    for (int mt = 0; mt < 2; ++mt) {
        #pragma unroll
        for (int half = 0; half < 2; ++half) {
            const int rloc = wm * 32 + mt * 16 + half * 8 + g;
            float* dst;
            bool valid;
            if (bm < 64) {
                const int r = bm * BM + rloc;
                const int b = r >> 8, tt = r & 255;
                dst = out + ((size_t)b * OUT_ROWS + 254 + tt) * D_ + n0 + wn * 64;
                valid = true;
            } else {
                const int r = (bm - 64) * BM + rloc;
                dst = g_cm + (size_t)r * D_ + n0 + wn * 64;
                valid = (r < CM_ROWS);
            }
            if (valid) {
                #pragma unroll
                for (int nt = 0; nt < 8; ++nt) {
                    float2 v = make_float2(c[mt][nt][half * 2], c[mt][nt][half * 2 + 1]);
                    *reinterpret_cast<float2*>(dst + nt * 8 + t * 2) = v;
                }
            }
        }
    }
}

// ---------------------------------------------------------------------------
// Copy/broadcast: rows 0:254 <- g_cm, 510:2046 <- memory[1022:], 2046: <- x
// ---------------------------------------------------------------------------
__global__ __launch_bounds__(256) void copy_kernel(
    const float* __restrict__ inputs, const float* __restrict__ memory,
    float* __restrict__ out)
{
    constexpr int F4    = D_ / 4;
    constexpr int R_CM  = CM_ROWS * F4;
    constexpr int R_MEM = R_CM + 1536 * F4;
    constexpr int PER_B = (CM_ROWS + 1536 + SEQ) * F4;
    const int total = BATCH * PER_B;

    const float4* cm4  = reinterpret_cast<const float4*>(g_cm);
    const float4* mem4 = reinterpret_cast<const float4*>(memory);
    const float4* in4  = reinterpret_cast<const float4*>(inputs);
    float4*       out4 = reinterpret_cast<float4*>(out);

    for (int idx = blockIdx.x * blockDim.x + threadIdx.x; idx < total;
         idx += gridDim.x * blockDim.x) {
        const int b = idx / PER_B;
        const int r = idx - b * PER_B;
        float4 v;
        size_t dst;
        const size_t base = (size_t)b * OUT_ROWS * F4;
        if (r < R_CM)       { v = cm4[r];                         dst = base + r; }
        else if (r < R_MEM) { int rr = r - R_CM;
                              v = mem4[1022 * F4 + rr];           dst = base + 510 * F4 + rr; }
        else                { int rr = r - R_MEM;
                              v = in4[(size_t)b * SEQ * F4 + rr]; dst = base + 2046 * F4 + rr; }
        out4[dst] = v;
    }
}

// ---------------------------------------------------------------------------
extern "C" void kernel_launch(void* const* d_in, const int* in_sizes, int n_in,
                              void* d_out, int out_size)
{
    const float* inputs  = (const float*)d_in[0];  // (32, 512, 1024)
    const float* memory  = (const float*)d_in[1];  // (2558, 1024)
    const float* filters = (const float*)d_in[2];  // (2, 1024, 1024) == B[k][n]
    float* out = (float*)d_out;                    // (32, 2558, 1024)

    cudaFuncSetAttribute(helix_gemm, cudaFuncAttributeMaxDynamicSharedMemorySize,
                         SMEM_BYTES);

    // 1) one tf32 mma.sync GEMM for both compress ops (M-tiles 0-63: inputs,
    //    64-65: memory rows -> g_cm)
    helix_gemm<<<dim3(D_ / BN, 66), 256, SMEM_BYTES>>>(
        inputs, memory + 2 * D_, filters, out);
    // 2) broadcast cm + memory tail + x passthrough
    copy_kernel<<<148 * 16, 256>>>(inputs, memory, out);
}

// round 5
// speedup vs baseline: 6.2050x; 1.4562x over previous
#include <cuda_runtime.h>
#include <cuda_fp16.h>
#include <cstdint>

// ============================================================================
// HelixMemory, fp16 mma.sync path (portable PTX; tf32->fp16: same 10-bit
// mantissa, 2x MAC rate):
//   out[b, 0:254]      = cm[r]   = memory[2r+2] @ F0 + memory[2r+3] @ F1
//   out[b, 254:510]    = cx[b,t] = x[b,2t] @ F0 + x[b,2t+1] @ F1
//   out[b, 510:2046]   = memory[1022:2558]
//   out[b, 2046:2558]  = x[b]
// Phase 1 (prep): fp16-convert A (inputs||memory rows -> 8448x2048) and
//   F^T (-> Bt[n][k]), plus all batch-independent out writes.
// Phase 2: one fp16 GEMM M=8448, N=1024, K=2048 (m16n8k16, fp32 accum).
// Phase 3: broadcast cm block.
// ============================================================================

namespace {
constexpr int D_       = 1024;
constexpr int KDIM     = 2048;
constexpr int OUT_ROWS = 2558;
constexpr int CM_ROWS  = 254;
constexpr int BATCH    = 32;
constexpr int SEQ      = 512;

constexpr int BM = 128, BN = 128, BK = 64;       // BK in fp16 elements
constexpr int STAGES = 3;
constexpr int KT = KDIM / BK;                    // 32

constexpr int PITCH_H  = BK + 8;                 // 72 halves = 144 B row pitch
constexpr int PITCH_U  = PITCH_H / 2;            // 36 uint32 per row
constexpr int TILE_H   = BM * PITCH_H;           // 9216 halves per tile
constexpr int STAGE_H  = 2 * TILE_H;             // A + B
constexpr int SMEM_BYTES = STAGES * STAGE_H * 2; // 110592 B
}

__device__ __align__(128) float g_cm[CM_ROWS * D_];                 // 1 MB
__device__ __align__(128) __half g_Ah[(BATCH * 256 + 256) * KDIM];  // 34.6 MB
__device__ __align__(128) __half g_Bt[D_ * KDIM];                   // 4 MB, [n][k]

// ---------------------------------------------------------------------------
__device__ __forceinline__ uint32_t smem_u32(const void* p) {
    uint32_t a;
    asm("{ .reg .u64 t; cvta.to.shared.u64 t, %1; cvt.u32.u64 %0, t; }" : "=r"(a) : "l"(p));
    return a;
}
__device__ __forceinline__ void cp16(uint32_t s, const void* g) {
    asm volatile("cp.async.cg.shared.global [%0], [%1], 16;" :: "r"(s), "l"(g));
}
__device__ __forceinline__ void mma_f16(float* c, const uint32_t* a, const uint32_t* b) {
    asm volatile(
        "mma.sync.aligned.m16n8k16.row.col.f32.f16.f16.f32 "
        "{%0,%1,%2,%3}, {%4,%5,%6,%7}, {%8,%9}, {%0,%1,%2,%3};"
        : "+f"(c[0]), "+f"(c[1]), "+f"(c[2]), "+f"(c[3])
        : "r"(a[0]), "r"(a[1]), "r"(a[2]), "r"(a[3]), "r"(b[0]), "r"(b[1]));
}
__device__ __forceinline__ uint32_t pack_h2(float x, float y) {
    __half2 h = __floats2half2_rn(x, y);
    return *reinterpret_cast<uint32_t*>(&h);
}

// ---------------------------------------------------------------------------
// prep 1: convert inputs -> g_Ah rows [0, 8192) AND out passthrough rows
// ---------------------------------------------------------------------------
__global__ __launch_bounds__(256) void conv_inputs(
    const float* __restrict__ inputs, float* __restrict__ out)
{
    constexpr int TOTAL = BATCH * SEQ * D_ / 4;          // f4 units: 4,194,304
    constexpr int PER_B = SEQ * D_ / 4;                  // 131072
    const float4* in4 = reinterpret_cast<const float4*>(inputs);
    float4*      out4 = reinterpret_cast<float4*>(out);
    uint2*       ah   = reinterpret_cast<uint2*>(g_Ah);

    for (int idx = blockIdx.x * blockDim.x + threadIdx.x; idx < TOTAL;
         idx += gridDim.x * blockDim.x) {
        float4 v = in4[idx];
        ah[idx] = make_uint2(pack_h2(v.x, v.y), pack_h2(v.z, v.w));
        const int b = idx / PER_B, rem = idx - b * PER_B;
        out4[(size_t)b * (OUT_ROWS * D_ / 4) + 2046 * (D_ / 4) + rem] = v;
    }
}

// ---------------------------------------------------------------------------
// prep 2: convert memory rows 2..513 -> g_Ah rows [8192, 8448)
// ---------------------------------------------------------------------------
__global__ __launch_bounds__(256) void conv_mem(const float* __restrict__ memory)
{
    constexpr int TOTAL = 256 * KDIM / 4;                // 131072 f4
    const float4* src = reinterpret_cast<const float4*>(memory + 2 * D_);
    uint2* ah = reinterpret_cast<uint2*>(g_Ah) + (size_t)BATCH * 256 * (KDIM / 4);
    for (int idx = blockIdx.x * blockDim.x + threadIdx.x; idx < TOTAL;
         idx += gridDim.x * blockDim.x) {
        float4 v = src[idx];
        ah[idx] = make_uint2(pack_h2(v.x, v.y), pack_h2(v.z, v.w));
    }
}

// ---------------------------------------------------------------------------
// prep 3: g_Bt[n][k] = fp16(F[k][n]); 64k x 32n tiles
// ---------------------------------------------------------------------------
__global__ __launch_bounds__(256) void conv_filters(const float* __restrict__ F)
{
    __shared__ float tile[64][33];
    const int n0 = blockIdx.x * 32;
    const int k0 = blockIdx.y * 64;
    const int tx = threadIdx.x, ty = threadIdx.y;      // 32 x 8
    #pragma unroll
    for (int i = ty; i < 64; i += 8)
        tile[i][tx] = F[(size_t)(k0 + i) * D_ + n0 + tx];
    __syncthreads();
    uint32_t* bt = reinterpret_cast<uint32_t*>(g_Bt);
    #pragma unroll
    for (int i = ty; i < 32; i += 8)                   // n row
        bt[(size_t)(n0 + i) * (KDIM / 2) + k0 / 2 + tx] =
            pack_h2(tile[2 * tx][i], tile[2 * tx + 1][i]);
}

// ---------------------------------------------------------------------------
// prep 4: out[b, 510:2046] = memory[1022:2558]
// ---------------------------------------------------------------------------
__global__ __launch_bounds__(256) void bcast_mem(
    const float* __restrict__ memory, float* __restrict__ out)
{
    constexpr int PER_B = 1536 * D_ / 4;               // 393216
    constexpr int TOTAL = BATCH * PER_B;
    const float4* mem4 = reinterpret_cast<const float4*>(memory) + 1022 * (D_ / 4);
    float4* out4 = reinterpret_cast<float4*>(out);
    for (int idx = blockIdx.x * blockDim.x + threadIdx.x; idx < TOTAL;
         idx += gridDim.x * blockDim.x) {
        const int b = idx / PER_B, rem = idx - b * PER_B;
        out4[(size_t)b * (OUT_ROWS * D_ / 4) + 510 * (D_ / 4) + rem] = mem4[rem];
    }
}

// ---------------------------------------------------------------------------
// post: out[b, 0:254] = g_cm
// ---------------------------------------------------------------------------
__global__ __launch_bounds__(256) void bcast_cm(float* __restrict__ out)
{
    constexpr int PER_B = CM_ROWS * D_ / 4;            // 65024
    constexpr int TOTAL = BATCH * PER_B;
    const float4* cm4 = reinterpret_cast<const float4*>(g_cm);
    float4* out4 = reinterpret_cast<float4*>(out);
    for (int idx = blockIdx.x * blockDim.x + threadIdx.x; idx < TOTAL;
         idx += gridDim.x * blockDim.x) {
        const int b = idx / PER_B, rem = idx - b * PER_B;
        out4[(size_t)b * (OUT_ROWS * D_ / 4) + rem] = cm4[rem];
    }
}

// ---------------------------------------------------------------------------
// fp16 GEMM: grid (8 N-tiles, 66 M-tiles). bm<64 -> scatter into out,
// bm>=64 -> g_cm. A = g_Ah (contiguous), B = g_Bt[n][k].
// ---------------------------------------------------------------------------
__global__ __launch_bounds__(256, 2) void helix_gemm(float* __restrict__ out)
{
    extern __shared__ __half smem_h[];
    const uint32_t sbase = smem_u32(smem_h);

    const int tid  = threadIdx.x;
    const int wid  = tid >> 5;
    const int lane = tid & 31;
    const int g    = lane >> 2;
    const int t    = lane & 3;
    const int wm   = wid & 3;          // 4 warps x 32 rows
    const int wn   = wid >> 2;         // 2 warps x 64 cols

    const int bn = blockIdx.x;
    const int bm = blockIdx.y;
    const int n0 = bn * BN;

    const __half* Abase = g_Ah + (size_t)bm * BM * KDIM;

    auto issue = [&](int kt) {
        const int s = kt % STAGES;
        const uint32_t sA = sbase + (uint32_t)(s * STAGE_H) * 2;
        const uint32_t sB = sA + (uint32_t)TILE_H * 2;
        const int k0 = kt * BK;
        #pragma unroll
        for (int i = 0; i < 4; ++i) {              // 1024 chunks of 16B each tile
            const int q   = tid + 256 * i;
            const int row = q >> 3;
            const int c   = q & 7;
            cp16(sA + (uint32_t)(row * PITCH_H + c * 8) * 2,
                 Abase + (size_t)row * KDIM + k0 + c * 8);
            cp16(sB + (uint32_t)(row * PITCH_H + c * 8) * 2,
                 g_Bt + (size_t)(n0 + row) * KDIM + k0 + c * 8);
        }
        asm volatile("cp.async.commit_group;" ::: "memory");
    };

    float c[2][8][4] = {};

    issue(0);
    issue(1);

    for (int kt = 0; kt < KT; ++kt) {
        asm volatile("cp.async.wait_group 1;" ::: "memory");
        __syncthreads();

        if (kt + STAGES - 1 < KT) issue(kt + STAGES - 1);

        const int s = kt % STAGES;
        const uint32_t* As = reinterpret_cast<const uint32_t*>(smem_h + s * STAGE_H);
        const uint32_t* Bs = As + TILE_H / 2;

        #pragma unroll
        for (int ks = 0; ks < 4; ++ks) {           // 4 x k16 = BK 64
            uint32_t a[2][4];
            #pragma unroll
            for (int mt = 0; mt < 2; ++mt) {
                const uint32_t* ap = As + (wm * 32 + mt * 16 + g) * PITCH_U + ks * 8 + t;
                a[mt][0] = ap[0];
                a[mt][1] = ap[8 * PITCH_U];
                a[mt][2] = ap[4];
                a[mt][3] = ap[8 * PITCH_U + 4];
            }
            uint32_t bf[8][2];
            #pragma unroll
            for (int nt = 0; nt < 8; ++nt) {
                const uint32_t* bp = Bs + (wn * 64 + nt * 8 + g) * PITCH_U + ks * 8 + t;
                bf[nt][0] = bp[0];
                bf[nt][1] = bp[4];
            }
            #pragma unroll
            for (int mt = 0; mt < 2; ++mt)
                #pragma unroll
                for (int nt = 0; nt < 8; ++nt)
                    mma_f16(c[mt][nt], a[mt], bf[nt]);
        }
        __syncthreads();
    }

    // ---- epilogue ----------------------------------------------------------
    #pragma unroll
    for (int mt = 0; mt < 2; ++mt) {
        #pragma unroll
        for (int half = 0; half < 2; ++half) {
            const int rloc = wm * 32 + mt * 16 + half * 8 + g;
            float* dst;
            bool valid;
            if (bm < 64) {
                const int r = bm * BM + rloc;
                const int b = r >> 8, tt = r & 255;
                dst = out + ((size_t)b * OUT_ROWS + 254 + tt) * D_ + n0 + wn * 64;
                valid = true;
            } else {
                const int r = (bm - 64) * BM + rloc;
                dst = g_cm + (size_t)r * D_ + n0 + wn * 64;
                valid = (r < CM_ROWS);
            }
            if (valid) {
                #pragma unroll
                for (int nt = 0; nt < 8; ++nt) {
                    float2 v = make_float2(c[mt][nt][half * 2], c[mt][nt][half * 2 + 1]);
                    *reinterpret_cast<float2*>(dst + nt * 8 + t * 2) = v;
                }
            }
        }
    }
}

// ---------------------------------------------------------------------------
extern "C" void kernel_launch(void* const* d_in, const int* in_sizes, int n_in,
                              void* d_out, int out_size)
{
    const float* inputs  = (const float*)d_in[0];  // (32, 512, 1024)
    const float* memory  = (const float*)d_in[1];  // (2558, 1024)
    const float* filters = (const float*)d_in[2];  // (2, 1024, 1024)
    float* out = (float*)d_out;                    // (32, 2558, 1024)

    cudaFuncSetAttribute(helix_gemm, cudaFuncAttributeMaxDynamicSharedMemorySize,
                         SMEM_BYTES);

    // prep: fp16 conversions + all batch-independent out regions
    conv_inputs <<<148 * 8, 256>>>(inputs, out);
    conv_mem    <<<128, 256>>>(memory);
    conv_filters<<<dim3(D_ / 32, KDIM / 64), dim3(32, 8)>>>(filters);
    bcast_mem   <<<148 * 8, 256>>>(memory, out);

    // fp16 tensor GEMM for both compress ops
    helix_gemm<<<dim3(D_ / BN, 66), 256, SMEM_BYTES>>>(out);

    // broadcast cm block
    bcast_cm<<<148 * 4, 256>>>(out);
}